// round 12
// baseline (speedup 1.0000x reference)
#include <cuda_runtime.h>
#include <math.h>
#include <stdint.h>

#define Bz   4
#define Nn   512
#define Dd   64
#define ED   32
#define KK   16
#define BN   (Bz*Nn)          // 2048
#define BNN  (Bz*Nn*Nn)       // 1048576
#define EPSf 1e-5f

// ---------------- scratch (static device memory; no allocs) ----------------
__device__ __align__(16) float g_x0[BN*Dd];
__device__ float                g_sq[BN];
__device__ __align__(16) float g_d2[BNN];
__device__ int                  g_idx[BN*KK];
__device__ __align__(16) float g_p[BN*Dd];
__device__ __align__(16) float g_q[BN*Dd];
__device__ float                g_part[128*2*Dd];
__device__ float                g_stats[2*Dd];
__device__ __align__(16) float g_n1[BN*Dd];
__device__ __align__(16) float g_n2[BN*Dd];
__device__ __align__(16) float g_A[BN*ED];
__device__ __align__(16) float g_Bt[BN*ED];
__device__ __align__(8)  float g_C[ED];
__device__ __align__(16) float g_W[ED*ED];

// ---------------- helpers ----------------
__device__ __forceinline__ float bred64(float v, volatile float* sred, int t){
    #pragma unroll
    for (int o=16;o;o>>=1) v += __shfl_xor_sync(0xffffffffu, v, o);
    __syncthreads();
    if ((t&31)==0) sred[t>>5] = v;
    __syncthreads();
    return sred[0] + sred[1];
}

__device__ __forceinline__ unsigned long long addf2(unsigned long long a, unsigned long long b){
    unsigned long long d;
    asm("add.rn.f32x2 %0, %1, %2;" : "=l"(d) : "l"(a), "l"(b));
    return d;
}
__device__ __forceinline__ void fmaf2(unsigned long long &d, unsigned long long a, unsigned long long b){
    asm("fma.rn.f32x2 %0, %1, %2, %0;" : "+l"(d) : "l"(a), "l"(b));
}
__device__ __forceinline__ unsigned long long dup2(float x){
    unsigned long long v;
    asm("mov.b64 %0, {%1, %1};" : "=l"(v) : "r"(__float_as_uint(x)));
    return v;
}
__device__ __forceinline__ float gelu_exact(float x){
    return 0.5f * x * (1.f + erff(x * 0.70710678118654752f));
}

// ---------------- K0: LayerNorm(H) -> g_x0, plus |row|^2 -> g_sq ----------------
__global__ void k_lnH(const float* __restrict__ H, const float* __restrict__ g,
                      const float* __restrict__ b){
    __shared__ float sred[2];
    int row = blockIdx.x, t = threadIdx.x;
    float v = H[row*Dd + t];
    float mean = bred64(v, sred, t) * (1.f/Dd);
    float d = v - mean;
    float var = bred64(d*d, sred, t) * (1.f/Dd);
    float xn = d * rsqrtf(var + EPSf) * g[t] + b[t];
    g_x0[row*Dd + t] = xn;
    float sq = bred64(xn*xn, sred, t);
    if (t == 0) g_sq[row] = sq;
}

// ---------------- K1: pairwise distance keys (one 32x32 tile per block) ----------------
__global__ void __launch_bounds__(256) k_dist(int layer){
    const float* __restrict__ x = layer ? g_n1 : g_x0;
    __shared__ float sxi[32][68];
    __shared__ float sxjT[64][33];
    __shared__ float ssqj[32];
    int b  = blockIdx.z;
    int i0 = blockIdx.y * 32;
    int j0 = blockIdx.x * 32;
    int t  = threadIdx.x;
    {
        int il = t >> 3, c0 = (t & 7) * 8;
        const float* srci = x + (size_t)(b*Nn + i0 + il)*Dd + c0;
        float4 a0 = *(const float4*)srci;
        float4 a1 = *(const float4*)(srci + 4);
        *(float4*)&sxi[il][c0]   = a0;
        *(float4*)&sxi[il][c0+4] = a1;
        const float* srcj = x + (size_t)(b*Nn + j0 + il)*Dd + c0;
        float4 b0 = *(const float4*)srcj;
        float4 b1 = *(const float4*)(srcj + 4);
        sxjT[c0+0][il]=b0.x; sxjT[c0+1][il]=b0.y; sxjT[c0+2][il]=b0.z; sxjT[c0+3][il]=b0.w;
        sxjT[c0+4][il]=b1.x; sxjT[c0+5][il]=b1.y; sxjT[c0+6][il]=b1.z; sxjT[c0+7][il]=b1.w;
        if (t < 32) ssqj[t] = g_sq[b*Nn + j0 + t];
    }
    __syncthreads();
    int w = t >> 5, lane = t & 31;
    int ib = w * 4;
    float a0=0.f, a1=0.f, a2=0.f, a3=0.f;
    #pragma unroll
    for (int c4 = 0; c4 < 16; c4++){
        float4 x0 = *(const float4*)&sxi[ib+0][c4*4];
        float4 x1 = *(const float4*)&sxi[ib+1][c4*4];
        float4 x2 = *(const float4*)&sxi[ib+2][c4*4];
        float4 x3 = *(const float4*)&sxi[ib+3][c4*4];
        float r0 = sxjT[c4*4+0][lane];
        float r1 = sxjT[c4*4+1][lane];
        float r2 = sxjT[c4*4+2][lane];
        float r3 = sxjT[c4*4+3][lane];
        a0 += x0.x*r0 + x0.y*r1 + x0.z*r2 + x0.w*r3;
        a1 += x1.x*r0 + x1.y*r1 + x1.z*r2 + x1.w*r3;
        a2 += x2.x*r0 + x2.y*r1 + x2.z*r2 + x2.w*r3;
        a3 += x3.x*r0 + x3.y*r1 + x3.z*r2 + x3.w*r3;
    }
    float sj = ssqj[lane];
    size_t base = (size_t)(b*Nn + i0 + ib) * Nn + j0 + lane;
    g_d2[base + 0*Nn] = sj - 2.f*a0;
    g_d2[base + 1*Nn] = sj - 2.f*a1;
    g_d2[base + 2*Nn] = sj - 2.f*a2;
    g_d2[base + 3*Nn] = sj - 2.f*a3;
}

// ---------------- K2: top-16 smallest per row ----------------
__global__ void k_topk(){
    int w = threadIdx.x >> 5, lane = threadIdx.x & 31;
    int row = blockIdx.x * 4 + w;
    const float* r = g_d2 + (size_t)row * Nn + lane * 16;
    float v[16];
    #pragma unroll
    for (int u = 0; u < 4; u++){
        float4 a = *(const float4*)(r + u*4);
        v[u*4]=a.x; v[u*4+1]=a.y; v[u*4+2]=a.z; v[u*4+3]=a.w;
    }
    unsigned used = 0;
    const float INF = __int_as_float(0x7f800000);
    for (int sel = 0; sel < KK; sel++){
        float bv = INF; int bu = 16;
        #pragma unroll
        for (int u = 0; u < 16; u++){
            bool ok = !((used >> u) & 1u);
            if (ok && v[u] < bv){ bv = v[u]; bu = u; }
        }
        int gi = lane * 16 + bu;
        #pragma unroll
        for (int o = 16; o; o >>= 1){
            float ov = __shfl_xor_sync(0xffffffffu, bv, o);
            int   og = __shfl_xor_sync(0xffffffffu, gi, o);
            if (ov < bv || (ov == bv && og < gi)){ bv = ov; gi = og; }
        }
        if ((gi >> 4) == lane) used |= 1u << (gi & 15);
        if (lane == 0) g_idx[row*KK + sel] = gi;
    }
}

// ---------------- K3: p2 = x@Wtop, q = x@Wbot, p = p2 - q (weights via LDG/L1) ----------------
__global__ void __launch_bounds__(256) k_pq(int layer, const float* __restrict__ mw){
    const float* __restrict__ x = layer ? g_n1 : g_x0;
    __shared__ __align__(16) float sx[1024];
    int t = threadIdx.x;
    int rowbase = blockIdx.x * 16;
    ((float4*)sx)[t] = ((const float4*)(x + (size_t)rowbase*64))[t];
    __syncthreads();
    int r = t >> 4, widx = t & 15;
    const float4* __restrict__ Wt = (const float4*)mw;
    const float4* __restrict__ Wb = (const float4*)(mw + 4096);
    float4 p2 = {0,0,0,0}, q = {0,0,0,0};
    #pragma unroll 8
    for (int c = 0; c < 64; c++){
        float xc = sx[r*64 + c];
        float4 wt = Wt[c*16 + widx];
        float4 wb = Wb[c*16 + widx];
        p2.x += xc*wt.x; p2.y += xc*wt.y; p2.z += xc*wt.z; p2.w += xc*wt.w;
        q.x  += xc*wb.x; q.y  += xc*wb.y; q.z  += xc*wb.z; q.w  += xc*wb.w;
    }
    float4 p;
    p.x = p2.x - q.x; p.y = p2.y - q.y; p.z = p2.z - q.z; p.w = p2.w - q.w;
    *(float4*)&g_p[(size_t)(rowbase + r)*64 + widx*4] = p;
    *(float4*)&g_q[(size_t)(rowbase + r)*64 + widx*4] = q;
}

// ---------------- K4: BN partial stats ----------------
__global__ void __launch_bounds__(256) k_stats(){
    __shared__ int sidx[256];
    __shared__ float ssum[16][64], ssq2[16][64];
    int t = threadIdx.x;
    int rowbase = blockIdx.x * 16;
    sidx[t] = g_idx[rowbase*KK + t];
    __syncthreads();
    int rl = t >> 4, c0 = (t & 15) * 4;
    int row = rowbase + rl, b = row >> 9;
    float4 p = *(const float4*)&g_p[(size_t)row*64 + c0];
    float4 s = {0,0,0,0}, ss = {0,0,0,0};
    #pragma unroll
    for (int k = 0; k < KK; k++){
        int j = sidx[rl*KK + k];
        float4 qv = *(const float4*)&g_q[(size_t)(b*Nn + j)*64 + c0];
        float h0 = p.x + qv.x, h1 = p.y + qv.y, h2 = p.z + qv.z, h3 = p.w + qv.w;
        s.x += h0; s.y += h1; s.z += h2; s.w += h3;
        ss.x += h0*h0; ss.y += h1*h1; ss.z += h2*h2; ss.w += h3*h3;
    }
    *(float4*)&ssum[rl][c0] = s;
    *(float4*)&ssq2[rl][c0] = ss;
    __syncthreads();
    if (t < 64){
        float a = 0.f, bb = 0.f;
        #pragma unroll
        for (int r2 = 0; r2 < 16; r2++){ a += ssum[r2][t]; bb += ssq2[r2][t]; }
        g_part[blockIdx.x*128 + t]      = a;
        g_part[blockIdx.x*128 + 64 + t] = bb;
    }
}

// ---------------- K5: reduce partials ----------------
__global__ void k_stats2(){
    int t = threadIdx.x;   // 128 threads
    float s = 0.f;
    #pragma unroll 8
    for (int blk = 0; blk < 128; blk++) s += g_part[blk*128 + t];
    g_stats[t] = s;
}

// ---------------- K6: n_out = mean_k gelu(BN(p + q_nbr)) ----------------
__global__ void __launch_bounds__(256) k_nout(int layer, const float* __restrict__ gam,
                                              const float* __restrict__ bet,
                                              float* __restrict__ outH){
    __shared__ int sidx[256];
    int t = threadIdx.x;
    int rowbase = blockIdx.x * 16;
    sidx[t] = g_idx[rowbase*KK + t];
    __syncthreads();
    int rl = t >> 4, c0 = (t & 15) * 4;
    int row = rowbase + rl, b = row >> 9;
    const float invN = 1.f / (float)(BN * KK);
    float4 st  = *(const float4*)&g_stats[c0];
    float4 st2 = *(const float4*)&g_stats[64 + c0];
    float4 ga  = *(const float4*)&gam[c0];
    float4 be  = *(const float4*)&bet[c0];
    float mu0 = st.x*invN, mu1 = st.y*invN, mu2 = st.z*invN, mu3 = st.w*invN;
    float rs0 = rsqrtf(st2.x*invN - mu0*mu0 + EPSf);
    float rs1 = rsqrtf(st2.y*invN - mu1*mu1 + EPSf);
    float rs2 = rsqrtf(st2.z*invN - mu2*mu2 + EPSf);
    float rs3 = rsqrtf(st2.w*invN - mu3*mu3 + EPSf);
    float4 p = *(const float4*)&g_p[(size_t)row*64 + c0];
    float4 acc = {0,0,0,0};
    #pragma unroll
    for (int k = 0; k < KK; k++){
        int j = sidx[rl*KK + k];
        float4 qv = *(const float4*)&g_q[(size_t)(b*Nn + j)*64 + c0];
        acc.x += gelu_exact((p.x + qv.x - mu0) * rs0 * ga.x + be.x);
        acc.y += gelu_exact((p.y + qv.y - mu1) * rs1 * ga.y + be.y);
        acc.z += gelu_exact((p.z + qv.z - mu2) * rs2 * ga.z + be.z);
        acc.w += gelu_exact((p.w + qv.w - mu3) * rs3 * ga.w + be.w);
    }
    float4 nv;
    nv.x = acc.x * (1.f/KK); nv.y = acc.y * (1.f/KK);
    nv.z = acc.z * (1.f/KK); nv.w = acc.w * (1.f/KK);
    if (layer){
        *(float4*)&g_n2[(size_t)row*64 + c0] = nv;
        *(float4*)&outH[(size_t)row*64 + c0] = nv;
    } else {
        *(float4*)&g_n1[(size_t)row*64 + c0] = nv;
        float sq = nv.x*nv.x + nv.y*nv.y + nv.z*nv.z + nv.w*nv.w;
        #pragma unroll
        for (int o = 8; o; o >>= 1) sq += __shfl_xor_sync(0xffffffffu, sq, o);
        if ((t & 15) == 0) g_sq[row] = sq;
    }
}

// ---------------- K8: A/Bt per row + (block 0) W, C fusion ----------------
__global__ void __launch_bounds__(256) k_abt(const float* __restrict__ hw,
                                             const float* __restrict__ hb){
    __shared__ float s_wn11[2048], s_wn21[2048], s_wn12[2048], s_wn22[2048], s_we2[1024];
    __shared__ float sn1[8][64], sn2[8][64], sa1[8][32], sb1[8][32];
    int t = threadIdx.x;
    for (int u = t; u < 2048; u += 256){
        s_wn11[u] = hw[1024 + u];
        s_wn21[u] = hw[3072 + u];
        s_wn12[u] = hw[5120 + 1024 + u];
        s_wn22[u] = hw[5120 + 3072 + u];
    }
    for (int u = t; u < 1024; u += 256) s_we2[u] = hw[5120 + u];
    int w = t >> 5, lane = t & 31;
    int row = blockIdx.x * 8 + w;
    sn1[w][lane]      = g_n1[(size_t)row*64 + lane];
    sn1[w][32 + lane] = g_n1[(size_t)row*64 + 32 + lane];
    sn2[w][lane]      = g_n2[(size_t)row*64 + lane];
    sn2[w][32 + lane] = g_n2[(size_t)row*64 + 32 + lane];
    __syncthreads();
    float a1 = 0.f, b1 = 0.f;
    #pragma unroll
    for (int d = 0; d < 64; d++){
        float nv = sn1[w][d];
        a1 += nv * s_wn11[d*32 + lane];
        b1 += nv * s_wn21[d*32 + lane];
    }
    sa1[w][lane] = a1; sb1[w][lane] = b1;
    __syncwarp();
    float A = 0.f, Bv = 0.f;
    #pragma unroll
    for (int e = 0; e < 32; e++){
        float w2 = s_we2[e*32 + lane];
        A  += sa1[w][e] * w2;
        Bv += sb1[w][e] * w2;
    }
    #pragma unroll
    for (int d = 0; d < 64; d++){
        float nv = sn2[w][d];
        A  += nv * s_wn12[d*32 + lane];
        Bv += nv * s_wn22[d*32 + lane];
    }
    g_A[(size_t)row*32 + lane]  = A;
    g_Bt[(size_t)row*32 + lane] = Bv;
    if (blockIdx.x == 0){
        for (int u = t; u < 1024; u += 256){
            int e = u >> 5, f = u & 31;
            float s = 0.f;
            #pragma unroll
            for (int m = 0; m < 32; m++) s += hw[e*32 + m] * s_we2[m*32 + f];
            g_W[u] = s;
        }
        if (t < 32){
            float c = hb[32 + t];
            #pragma unroll
            for (int m = 0; m < 32; m++) c += hb[m] * s_we2[m*32 + t];
            g_C[t] = c;
        }
    }
}

// ---------------- K10: big fused E pass, 2 threads per row (e-split GEMM) ----------------
// out_E[b,i,j,:] = LN(E[b,i,j,:]) @ W + A[b,j] + Bt[b,i] + C
// grid (32 jt, 64 it, 4 b), block 256 = 128 rows (8 i x 16 j), pair (t, t^1) per row.
__global__ void __launch_bounds__(256) k_bigE(const float* __restrict__ E,
                                              const float* __restrict__ lnEg,
                                              const float* __restrict__ lnEb,
                                              float* __restrict__ outE){
    __shared__ __align__(16) unsigned long long sW[512];  // [e][f2]
    __shared__ __align__(8)  float sC[32];
    __shared__ float sg[32], sb[32];
    __shared__ __align__(16) float sA[16][36];
    __shared__ __align__(16) float sBt[8][36];
    int t = threadIdx.x;
    int b = blockIdx.z, i0 = blockIdx.y * 8, j0 = blockIdx.x * 16;
    {
        const unsigned long long* Wp = (const unsigned long long*)g_W;
        for (int u = t; u < 512; u += 256) sW[u] = Wp[u];
        if (t < 32){ sC[t] = g_C[t]; sg[t] = lnEg[t]; sb[t] = lnEb[t]; }
        for (int u = t; u < 512; u += 256){
            int r = u >> 5, f = u & 31;
            sA[r][f] = g_A[(size_t)(b*Nn + j0 + r)*32 + f];
        }
        {
            int r = t >> 5, f = t & 31;    // 256 threads = exactly 8x32
            sBt[r][f] = g_Bt[(size_t)(b*Nn + i0 + r)*32 + f];
        }
    }
    __syncthreads();
    int r = t >> 1, h = t & 1;
    int il = r >> 4, jl = r & 15;
    size_t row = (size_t)(b*Nn + i0 + il) * Nn + (j0 + jl);
    const float4* Er = (const float4*)(E + row*32 + h*16);

    float v[16];
    float s = 0.f;
    #pragma unroll
    for (int u = 0; u < 4; u++){
        float4 a = Er[u];
        v[u*4]=a.x; v[u*4+1]=a.y; v[u*4+2]=a.z; v[u*4+3]=a.w;
        s += a.x + a.y + a.z + a.w;
    }
    s += __shfl_xor_sync(0xffffffffu, s, 1);
    float mean = s * (1.f/32.f);
    float s2 = 0.f;
    #pragma unroll
    for (int u = 0; u < 16; u++){ float d = v[u] - mean; v[u] = d; s2 += d*d; }
    s2 += __shfl_xor_sync(0xffffffffu, s2, 1);
    float rstd = rsqrtf(s2 * (1.f/32.f) + EPSf);
    #pragma unroll
    for (int u = 0; u < 16; u++) v[u] = v[u] * rstd * sg[h*16 + u] + sb[h*16 + u];

    // acc init: h=0 gets A[jl]+C, h=1 gets Bt[il]  (sums to A+Bt+C after combine)
    const unsigned long long* Ap  = (const unsigned long long*)&sA[jl][0];
    const unsigned long long* Bp  = (const unsigned long long*)&sBt[il][0];
    const unsigned long long* Cp  = (const unsigned long long*)sC;
    unsigned long long acc[16];
    #pragma unroll
    for (int f2 = 0; f2 < 16; f2++)
        acc[f2] = h ? Bp[f2] : addf2(Ap[f2], Cp[f2]);

    // e-split GEMM: this thread covers e = h*16 .. h*16+15
    int ebase = h * 16;
    #pragma unroll
    for (int u = 0; u < 16; u++){
        unsigned long long vv = dup2(v[u]);
        #pragma unroll
        for (int f2 = 0; f2 < 16; f2++) fmaf2(acc[f2], vv, sW[(ebase + u)*16 + f2]);
    }

    // pair combine + write own f-half: thread h writes f2 in [h*8, h*8+8)
    float4* Or = (float4*)(outE + row*32 + h*16);
    #pragma unroll
    for (int k = 0; k < 8; k++){
        unsigned long long a_lo = acc[k];        // partial for f2 = k      (h=0's half)
        unsigned long long a_hi = acc[8 + k];    // partial for f2 = 8 + k  (h=1's half)
        unsigned long long send = h ? a_lo : a_hi;   // what partner needs
        unsigned long long mine = h ? a_hi : a_lo;   // my own half's partial
        unsigned long long recv = __shfl_xor_sync(0xffffffffu, send, 1);
        unsigned long long tot  = addf2(mine, recv);
        ((float2*)Or)[k] = *(float2*)&tot;
    }
}

// ---------------- launch ----------------
extern "C" void kernel_launch(void* const* d_in, const int* in_sizes, int n_in,
                              void* d_out, int out_size){
    const float* H    = (const float*)d_in[0];
    const float* E    = (const float*)d_in[1];
    const float* mlp  = (const float*)d_in[2];
    const float* bng  = (const float*)d_in[3];
    const float* bnb  = (const float*)d_in[4];
    const float* hw   = (const float*)d_in[5];
    const float* hb   = (const float*)d_in[6];
    const float* lnHg = (const float*)d_in[7];
    const float* lnHb = (const float*)d_in[8];
    const float* lnEg = (const float*)d_in[9];
    const float* lnEb = (const float*)d_in[10];
    float* outH = (float*)d_out;
    float* outE = outH + BN*Dd;

    k_lnH<<<BN, 64>>>(H, lnHg, lnHb);
    for (int l = 0; l < 2; l++){
        k_dist<<<dim3(16,16,4), 256>>>(l);
        k_topk<<<512, 128>>>();
        k_pq<<<128, 256>>>(l, mlp + l*2*Dd*Dd);
        k_stats<<<128, 256>>>();
        k_stats2<<<1, 128>>>();
        k_nout<<<128, 256>>>(l, bng + l*Dd, bnb + l*Dd, outH);
    }
    k_abt<<<256, 256>>>(hw, hb);
    k_bigE<<<dim3(32,64,4), 256>>>(E, lnEg, lnEb, outE);
}

// round 15
// speedup vs baseline: 1.3767x; 1.3767x over previous
#include <cuda_runtime.h>
#include <math.h>
#include <stdint.h>

#define Bz   4
#define Nn   512
#define Dd   64
#define ED   32
#define KK   16
#define BN   (Bz*Nn)          // 2048
#define BNN  (Bz*Nn*Nn)       // 1048576
#define EPSf 1e-5f

// ---------------- scratch (static device memory; no allocs) ----------------
__device__ __align__(16) float g_x0[BN*Dd];
__device__ float                g_sq[BN];
__device__ __align__(16) float g_d2[BNN];
__device__ int                  g_idx[BN*KK];
__device__ __align__(16) float g_p[BN*Dd];
__device__ __align__(16) float g_q[BN*Dd];
__device__ float                g_part[128*2*Dd];
__device__ __align__(16) float g_n1[BN*Dd];
__device__ __align__(16) float g_n2[BN*Dd];
__device__ __align__(16) float g_A[BN*ED];
__device__ __align__(16) float g_Bt[BN*ED];
__device__ __align__(8)  float g_C[ED];
__device__ __align__(16) float g_W[ED*ED];

// ---------------- helpers ----------------
__device__ __forceinline__ float bred64(float v, volatile float* sred, int t){
    #pragma unroll
    for (int o=16;o;o>>=1) v += __shfl_xor_sync(0xffffffffu, v, o);
    __syncthreads();
    if ((t&31)==0) sred[t>>5] = v;
    __syncthreads();
    return sred[0] + sred[1];
}

__device__ __forceinline__ unsigned long long addf2(unsigned long long a, unsigned long long b){
    unsigned long long d;
    asm("add.rn.f32x2 %0, %1, %2;" : "=l"(d) : "l"(a), "l"(b));
    return d;
}
__device__ __forceinline__ void fmaf2(unsigned long long &d, unsigned long long a, unsigned long long b){
    asm("fma.rn.f32x2 %0, %1, %2, %0;" : "+l"(d) : "l"(a), "l"(b));
}
__device__ __forceinline__ unsigned long long dup2(float x){
    unsigned long long v;
    asm("mov.b64 %0, {%1, %1};" : "=l"(v) : "r"(__float_as_uint(x)));
    return v;
}
__device__ __forceinline__ float gelu_exact(float x){
    return 0.5f * x * (1.f + erff(x * 0.70710678118654752f));
}

// ---------------- K0: LayerNorm(H) -> g_x0, plus |row|^2 -> g_sq ----------------
__global__ void k_lnH(const float* __restrict__ H, const float* __restrict__ g,
                      const float* __restrict__ b){
    __shared__ float sred[2];
    int row = blockIdx.x, t = threadIdx.x;
    float v = H[row*Dd + t];
    float mean = bred64(v, sred, t) * (1.f/Dd);
    float d = v - mean;
    float var = bred64(d*d, sred, t) * (1.f/Dd);
    float xn = d * rsqrtf(var + EPSf) * g[t] + b[t];
    g_x0[row*Dd + t] = xn;
    float sq = bred64(xn*xn, sred, t);
    if (t == 0) g_sq[row] = sq;
}

// ---------------- K1: pairwise distance keys (one 32x32 tile per block) ----------------
__global__ void __launch_bounds__(256) k_dist(int layer){
    const float* __restrict__ x = layer ? g_n1 : g_x0;
    __shared__ float sxi[32][68];
    __shared__ float sxjT[64][33];
    __shared__ float ssqj[32];
    int b  = blockIdx.z;
    int i0 = blockIdx.y * 32;
    int j0 = blockIdx.x * 32;
    int t  = threadIdx.x;
    {
        int il = t >> 3, c0 = (t & 7) * 8;
        const float* srci = x + (size_t)(b*Nn + i0 + il)*Dd + c0;
        float4 a0 = *(const float4*)srci;
        float4 a1 = *(const float4*)(srci + 4);
        *(float4*)&sxi[il][c0]   = a0;
        *(float4*)&sxi[il][c0+4] = a1;
        const float* srcj = x + (size_t)(b*Nn + j0 + il)*Dd + c0;
        float4 b0 = *(const float4*)srcj;
        float4 b1 = *(const float4*)(srcj + 4);
        sxjT[c0+0][il]=b0.x; sxjT[c0+1][il]=b0.y; sxjT[c0+2][il]=b0.z; sxjT[c0+3][il]=b0.w;
        sxjT[c0+4][il]=b1.x; sxjT[c0+5][il]=b1.y; sxjT[c0+6][il]=b1.z; sxjT[c0+7][il]=b1.w;
        if (t < 32) ssqj[t] = g_sq[b*Nn + j0 + t];
    }
    __syncthreads();
    int w = t >> 5, lane = t & 31;
    int ib = w * 4;
    float a0=0.f, a1=0.f, a2=0.f, a3=0.f;
    #pragma unroll
    for (int c4 = 0; c4 < 16; c4++){
        float4 x0 = *(const float4*)&sxi[ib+0][c4*4];
        float4 x1 = *(const float4*)&sxi[ib+1][c4*4];
        float4 x2 = *(const float4*)&sxi[ib+2][c4*4];
        float4 x3 = *(const float4*)&sxi[ib+3][c4*4];
        float r0 = sxjT[c4*4+0][lane];
        float r1 = sxjT[c4*4+1][lane];
        float r2 = sxjT[c4*4+2][lane];
        float r3 = sxjT[c4*4+3][lane];
        a0 += x0.x*r0 + x0.y*r1 + x0.z*r2 + x0.w*r3;
        a1 += x1.x*r0 + x1.y*r1 + x1.z*r2 + x1.w*r3;
        a2 += x2.x*r0 + x2.y*r1 + x2.z*r2 + x2.w*r3;
        a3 += x3.x*r0 + x3.y*r1 + x3.z*r2 + x3.w*r3;
    }
    float sj = ssqj[lane];
    size_t base = (size_t)(b*Nn + i0 + ib) * Nn + j0 + lane;
    g_d2[base + 0*Nn] = sj - 2.f*a0;
    g_d2[base + 1*Nn] = sj - 2.f*a1;
    g_d2[base + 2*Nn] = sj - 2.f*a2;
    g_d2[base + 3*Nn] = sj - 2.f*a3;
}

// ---------------- K2: top-16 smallest per row ----------------
__global__ void k_topk(){
    int w = threadIdx.x >> 5, lane = threadIdx.x & 31;
    int row = blockIdx.x * 4 + w;
    const float* r = g_d2 + (size_t)row * Nn + lane * 16;
    float v[16];
    #pragma unroll
    for (int u = 0; u < 4; u++){
        float4 a = *(const float4*)(r + u*4);
        v[u*4]=a.x; v[u*4+1]=a.y; v[u*4+2]=a.z; v[u*4+3]=a.w;
    }
    unsigned used = 0;
    const float INF = __int_as_float(0x7f800000);
    for (int sel = 0; sel < KK; sel++){
        float bv = INF; int bu = 16;
        #pragma unroll
        for (int u = 0; u < 16; u++){
            bool ok = !((used >> u) & 1u);
            if (ok && v[u] < bv){ bv = v[u]; bu = u; }
        }
        int gi = lane * 16 + bu;   // ties -> lowest j (stable, matches jax)
        #pragma unroll
        for (int o = 16; o; o >>= 1){
            float ov = __shfl_xor_sync(0xffffffffu, bv, o);
            int   og = __shfl_xor_sync(0xffffffffu, gi, o);
            if (ov < bv || (ov == bv && og < gi)){ bv = ov; gi = og; }
        }
        if ((gi >> 4) == lane) used |= 1u << (gi & 15);
        if (lane == 0) g_idx[row*KK + sel] = gi;
    }
}

// ---------------- K3: p = x@(Wt-Wb), q = x@Wb (smem-staged, float4 LDS) ----------------
// REVERTED to the measured-8.5us round-2 form.
__global__ void __launch_bounds__(256) k_pq(int layer, const float* __restrict__ mw){
    const float* __restrict__ x = layer ? g_n1 : g_x0;
    __shared__ __align__(16) float swd[4096];
    __shared__ __align__(16) float swb[4096];
    __shared__ __align__(16) float sx[1024];
    int t = threadIdx.x;
    for (int u = t; u < 1024; u += 256){
        float4 top = ((const float4*)mw)[u];
        float4 bot = ((const float4*)(mw + 4096))[u];
        float4 dd;
        dd.x = top.x - bot.x; dd.y = top.y - bot.y;
        dd.z = top.z - bot.z; dd.w = top.w - bot.w;
        ((float4*)swb)[u] = bot;
        ((float4*)swd)[u] = dd;
    }
    int rowbase = blockIdx.x * 16;
    ((float4*)sx)[t] = ((const float4*)(x + (size_t)rowbase*64))[t];
    __syncthreads();
    int r = t >> 4, d0 = (t & 15) * 4;
    float4 p = {0,0,0,0}, q = {0,0,0,0};
    #pragma unroll
    for (int c = 0; c < 64; c++){
        float xc = sx[r*64 + c];
        float4 wd = *(const float4*)&swd[c*64 + d0];
        float4 wb = *(const float4*)&swb[c*64 + d0];
        p.x += xc*wd.x; p.y += xc*wd.y; p.z += xc*wd.z; p.w += xc*wd.w;
        q.x += xc*wb.x; q.y += xc*wb.y; q.z += xc*wb.z; q.w += xc*wb.w;
    }
    *(float4*)&g_p[(size_t)(rowbase + r)*64 + d0] = p;
    *(float4*)&g_q[(size_t)(rowbase + r)*64 + d0] = q;
}

// ---------------- K4: BN partial stats ----------------
__global__ void __launch_bounds__(256) k_stats(){
    __shared__ int sidx[256];
    __shared__ float ssum[16][64], ssq2[16][64];
    int t = threadIdx.x;
    int rowbase = blockIdx.x * 16;
    sidx[t] = g_idx[rowbase*KK + t];
    __syncthreads();
    int rl = t >> 4, c0 = (t & 15) * 4;
    int row = rowbase + rl, b = row >> 9;
    float4 p = *(const float4*)&g_p[(size_t)row*64 + c0];
    float4 s = {0,0,0,0}, ss = {0,0,0,0};
    #pragma unroll
    for (int k = 0; k < KK; k++){
        int j = sidx[rl*KK + k];
        float4 qv = *(const float4*)&g_q[(size_t)(b*Nn + j)*64 + c0];
        float h0 = p.x + qv.x, h1 = p.y + qv.y, h2 = p.z + qv.z, h3 = p.w + qv.w;
        s.x += h0; s.y += h1; s.z += h2; s.w += h3;
        ss.x += h0*h0; ss.y += h1*h1; ss.z += h2*h2; ss.w += h3*h3;
    }
    *(float4*)&ssum[rl][c0] = s;
    *(float4*)&ssq2[rl][c0] = ss;
    __syncthreads();
    if (t < 64){
        float a = 0.f, bb = 0.f;
        #pragma unroll
        for (int r2 = 0; r2 < 16; r2++){ a += ssum[r2][t]; bb += ssq2[r2][t]; }
        g_part[blockIdx.x*128 + t]      = a;
        g_part[blockIdx.x*128 + 64 + t] = bb;
    }
}

// ---------------- K6: n_out = mean_k gelu(BN(p + q_nbr)); stats2 FUSED in ----------------
// Each block redundantly reduces the 128x128 partials from hot L2 (fixed order).
__global__ void __launch_bounds__(256) k_nout(int layer, const float* __restrict__ gam,
                                              const float* __restrict__ bet,
                                              float* __restrict__ outH){
    __shared__ int sidx[256];
    __shared__ __align__(16) float sstats[128];
    __shared__ float stmp[2][128];
    int t = threadIdx.x;
    int rowbase = blockIdx.x * 16;
    {   // fused k_stats2: deterministic 2-phase reduction of g_part
        int c = t & 127, half = t >> 7;
        float s = 0.f;
        int b0 = half * 64;
        #pragma unroll 8
        for (int blk = b0; blk < b0 + 64; blk++) s += g_part[blk*128 + c];
        stmp[half][c] = s;
    }
    sidx[t] = g_idx[rowbase*KK + t];
    __syncthreads();
    if (t < 128) sstats[t] = stmp[0][t] + stmp[1][t];
    __syncthreads();
    int rl = t >> 4, c0 = (t & 15) * 4;
    int row = rowbase + rl, b = row >> 9;
    const float invN = 1.f / (float)(BN * KK);
    float4 st  = *(const float4*)&sstats[c0];
    float4 st2 = *(const float4*)&sstats[64 + c0];
    float4 ga  = *(const float4*)&gam[c0];
    float4 be  = *(const float4*)&bet[c0];
    float mu0 = st.x*invN, mu1 = st.y*invN, mu2 = st.z*invN, mu3 = st.w*invN;
    float rs0 = rsqrtf(st2.x*invN - mu0*mu0 + EPSf);
    float rs1 = rsqrtf(st2.y*invN - mu1*mu1 + EPSf);
    float rs2 = rsqrtf(st2.z*invN - mu2*mu2 + EPSf);
    float rs3 = rsqrtf(st2.w*invN - mu3*mu3 + EPSf);
    float4 p = *(const float4*)&g_p[(size_t)row*64 + c0];
    float4 acc = {0,0,0,0};
    #pragma unroll
    for (int k = 0; k < KK; k++){
        int j = sidx[rl*KK + k];
        float4 qv = *(const float4*)&g_q[(size_t)(b*Nn + j)*64 + c0];
        acc.x += gelu_exact((p.x + qv.x - mu0) * rs0 * ga.x + be.x);
        acc.y += gelu_exact((p.y + qv.y - mu1) * rs1 * ga.y + be.y);
        acc.z += gelu_exact((p.z + qv.z - mu2) * rs2 * ga.z + be.z);
        acc.w += gelu_exact((p.w + qv.w - mu3) * rs3 * ga.w + be.w);
    }
    float4 nv;
    nv.x = acc.x * (1.f/KK); nv.y = acc.y * (1.f/KK);
    nv.z = acc.z * (1.f/KK); nv.w = acc.w * (1.f/KK);
    if (layer){
        *(float4*)&g_n2[(size_t)row*64 + c0] = nv;
        *(float4*)&outH[(size_t)row*64 + c0] = nv;
    } else {
        *(float4*)&g_n1[(size_t)row*64 + c0] = nv;
        float sq = nv.x*nv.x + nv.y*nv.y + nv.z*nv.z + nv.w*nv.w;
        #pragma unroll
        for (int o = 8; o; o >>= 1) sq += __shfl_xor_sync(0xffffffffu, sq, o);
        if ((t & 15) == 0) g_sq[row] = sq;
    }
}

// ---------------- K8: A/Bt per row + (block 0) W, C fusion ----------------
__global__ void __launch_bounds__(256) k_abt(const float* __restrict__ hw,
                                             const float* __restrict__ hb){
    __shared__ float s_wn11[2048], s_wn21[2048], s_wn12[2048], s_wn22[2048], s_we2[1024];
    __shared__ float sn1[8][64], sn2[8][64], sa1[8][32], sb1[8][32];
    int t = threadIdx.x;
    for (int u = t; u < 2048; u += 256){
        s_wn11[u] = hw[1024 + u];
        s_wn21[u] = hw[3072 + u];
        s_wn12[u] = hw[5120 + 1024 + u];
        s_wn22[u] = hw[5120 + 3072 + u];
    }
    for (int u = t; u < 1024; u += 256) s_we2[u] = hw[5120 + u];
    int w = t >> 5, lane = t & 31;
    int row = blockIdx.x * 8 + w;
    sn1[w][lane]      = g_n1[(size_t)row*64 + lane];
    sn1[w][32 + lane] = g_n1[(size_t)row*64 + 32 + lane];
    sn2[w][lane]      = g_n2[(size_t)row*64 + lane];
    sn2[w][32 + lane] = g_n2[(size_t)row*64 + 32 + lane];
    __syncthreads();
    float a1 = 0.f, b1 = 0.f;
    #pragma unroll
    for (int d = 0; d < 64; d++){
        float nv = sn1[w][d];
        a1 += nv * s_wn11[d*32 + lane];
        b1 += nv * s_wn21[d*32 + lane];
    }
    sa1[w][lane] = a1; sb1[w][lane] = b1;
    __syncwarp();
    float A = 0.f, Bv = 0.f;
    #pragma unroll
    for (int e = 0; e < 32; e++){
        float w2 = s_we2[e*32 + lane];
        A  += sa1[w][e] * w2;
        Bv += sb1[w][e] * w2;
    }
    #pragma unroll
    for (int d = 0; d < 64; d++){
        float nv = sn2[w][d];
        A  += nv * s_wn12[d*32 + lane];
        Bv += nv * s_wn22[d*32 + lane];
    }
    g_A[(size_t)row*32 + lane]  = A;
    g_Bt[(size_t)row*32 + lane] = Bv;
    if (blockIdx.x == 0){
        for (int u = t; u < 1024; u += 256){
            int e = u >> 5, f = u & 31;
            float s = 0.f;
            #pragma unroll
            for (int m = 0; m < 32; m++) s += hw[e*32 + m] * s_we2[m*32 + f];
            g_W[u] = s;
        }
        if (t < 32){
            float c = hb[32 + t];
            #pragma unroll
            for (int m = 0; m < 32; m++) c += hb[m] * s_we2[m*32 + t];
            g_C[t] = c;
        }
    }
}

// ---------------- K10: big fused E pass (REVERTED to thread-per-row) ----------------
// out_E[b,i,j,:] = LN(E[b,i,j,:]) @ W + A[b,j] + Bt[b,i] + C
// grid (32 jt, 32 it, 4 b), block 256 (16 i x 16 j), thread-per-row, f32x2 FMA.
__global__ void __launch_bounds__(256) k_bigE(const float* __restrict__ E,
                                              const float* __restrict__ lnEg,
                                              const float* __restrict__ lnEb,
                                              float* __restrict__ outE){
    __shared__ __align__(16) unsigned long long sW[512];  // [e][f2] packed pairs
    __shared__ __align__(8)  float sC[32];
    __shared__ float sg[32], sb[32];
    __shared__ __align__(16) float sA[16][36], sBt[16][36];
    int t = threadIdx.x;
    int b = blockIdx.z, i0 = blockIdx.y * 16, j0 = blockIdx.x * 16;
    {
        const unsigned long long* Wp = (const unsigned long long*)g_W;
        for (int u = t; u < 512; u += 256) sW[u] = Wp[u];
        if (t < 32){ sC[t] = g_C[t]; sg[t] = lnEg[t]; sb[t] = lnEb[t]; }
        for (int u = t; u < 512; u += 256){
            int r = u >> 5, f = u & 31;
            sA[r][f]  = g_A [(size_t)(b*Nn + j0 + r)*32 + f];
            sBt[r][f] = g_Bt[(size_t)(b*Nn + i0 + r)*32 + f];
        }
    }
    __syncthreads();
    int il = t >> 4, jl = t & 15;
    size_t row = (size_t)(b*Nn + i0 + il) * Nn + (j0 + jl);
    const float4* Er = (const float4*)(E + row * 32);

    float v[32];
    float s = 0.f;
    #pragma unroll
    for (int u = 0; u < 8; u++){
        float4 a = Er[u];
        v[u*4]=a.x; v[u*4+1]=a.y; v[u*4+2]=a.z; v[u*4+3]=a.w;
        s += a.x + a.y + a.z + a.w;
    }
    float mean = s * (1.f/32.f);
    float s2 = 0.f;
    #pragma unroll
    for (int u = 0; u < 32; u++){ float d = v[u] - mean; v[u] = d; s2 += d*d; }
    float rstd = rsqrtf(s2 * (1.f/32.f) + EPSf);
    #pragma unroll
    for (int u = 0; u < 32; u++) v[u] = v[u] * rstd * sg[u] + sb[u];

    // acc init = A + Bt + C  (packed f32x2)
    const unsigned long long* Ap  = (const unsigned long long*)&sA[jl][0];
    const unsigned long long* Bp  = (const unsigned long long*)&sBt[il][0];
    const unsigned long long* Cp  = (const unsigned long long*)sC;
    unsigned long long accp[16];
    #pragma unroll
    for (int f2 = 0; f2 < 16; f2++) accp[f2] = addf2(addf2(Ap[f2], Bp[f2]), Cp[f2]);

    #pragma unroll
    for (int e = 0; e < 32; e++){
        unsigned long long vv = dup2(v[e]);
        #pragma unroll
        for (int f2 = 0; f2 < 16; f2++) fmaf2(accp[f2], vv, sW[e*16 + f2]);
    }

    float4* Or = (float4*)(outE + row * 32);
    #pragma unroll
    for (int u = 0; u < 8; u++){
        unsigned long long lo = accp[u*2], hi = accp[u*2 + 1];
        float4 o;
        o.x = __uint_as_float((unsigned)lo);
        o.y = __uint_as_float((unsigned)(lo >> 32));
        o.z = __uint_as_float((unsigned)hi);
        o.w = __uint_as_float((unsigned)(hi >> 32));
        Or[u] = o;
    }
}

// ---------------- launch ----------------
extern "C" void kernel_launch(void* const* d_in, const int* in_sizes, int n_in,
                              void* d_out, int out_size){
    const float* H    = (const float*)d_in[0];
    const float* E    = (const float*)d_in[1];
    const float* mlp  = (const float*)d_in[2];
    const float* bng  = (const float*)d_in[3];
    const float* bnb  = (const float*)d_in[4];
    const float* hw   = (const float*)d_in[5];
    const float* hb   = (const float*)d_in[6];
    const float* lnHg = (const float*)d_in[7];
    const float* lnHb = (const float*)d_in[8];
    const float* lnEg = (const float*)d_in[9];
    const float* lnEb = (const float*)d_in[10];
    float* outH = (float*)d_out;
    float* outE = outH + BN*Dd;

    k_lnH<<<BN, 64>>>(H, lnHg, lnHb);
    for (int l = 0; l < 2; l++){
        k_dist<<<dim3(16,16,4), 256>>>(l);
        k_topk<<<512, 128>>>();
        k_pq<<<128, 256>>>(l, mlp + l*2*Dd*Dd);
        k_stats<<<128, 256>>>();
        k_nout<<<128, 256>>>(l, bng + l*Dd, bnb + l*Dd, outH);
    }
    k_abt<<<256, 256>>>(hw, hb);
    k_bigE<<<dim3(32,32,4), 256>>>(E, lnEg, lnEb, outE);
}

// round 17
// speedup vs baseline: 1.5306x; 1.1117x over previous
#include <cuda_runtime.h>
#include <math.h>
#include <stdint.h>

#define Bz   4
#define Nn   512
#define Dd   64
#define ED   32
#define KK   16
#define BN   (Bz*Nn)          // 2048
#define BNN  (Bz*Nn*Nn)       // 1048576
#define EPSf 1e-5f

// ---------------- scratch (static device memory; no allocs) ----------------
__device__ __align__(16) float g_x0[BN*Dd];
__device__ float                g_sq[BN];
__device__ __align__(16) float g_d2[BNN];
__device__ int                  g_idx[BN*KK];
__device__ __align__(16) float g_p[BN*Dd];
__device__ __align__(16) float g_q[BN*Dd];
__device__ float                g_part[128*2*Dd];
__device__ __align__(16) float g_n1[BN*Dd];
__device__ __align__(16) float g_n2[BN*Dd];
__device__ __align__(16) float g_A[BN*ED];
__device__ __align__(16) float g_Bt[BN*ED];
__device__ __align__(8)  float g_C[ED];
__device__ __align__(16) float g_W[ED*ED];

// ---------------- helpers ----------------
__device__ __forceinline__ float bred64(float v, volatile float* sred, int t){
    #pragma unroll
    for (int o=16;o;o>>=1) v += __shfl_xor_sync(0xffffffffu, v, o);
    __syncthreads();
    if ((t&31)==0) sred[t>>5] = v;
    __syncthreads();
    return sred[0] + sred[1];
}

__device__ __forceinline__ unsigned long long addf2(unsigned long long a, unsigned long long b){
    unsigned long long d;
    asm("add.rn.f32x2 %0, %1, %2;" : "=l"(d) : "l"(a), "l"(b));
    return d;
}
__device__ __forceinline__ void fmaf2(unsigned long long &d, unsigned long long a, unsigned long long b){
    asm("fma.rn.f32x2 %0, %1, %2, %0;" : "+l"(d) : "l"(a), "l"(b));
}
__device__ __forceinline__ unsigned long long dup2(float x){
    unsigned long long v;
    asm("mov.b64 %0, {%1, %1};" : "=l"(v) : "r"(__float_as_uint(x)));
    return v;
}
__device__ __forceinline__ float gelu_exact(float x){
    return 0.5f * x * (1.f + erff(x * 0.70710678118654752f));
}

// ---------------- K0: LayerNorm(H) -> g_x0, plus |row|^2 -> g_sq ----------------
__global__ void k_lnH(const float* __restrict__ H, const float* __restrict__ g,
                      const float* __restrict__ b){
    __shared__ float sred[2];
    int row = blockIdx.x, t = threadIdx.x;
    float v = H[row*Dd + t];
    float mean = bred64(v, sred, t) * (1.f/Dd);
    float d = v - mean;
    float var = bred64(d*d, sred, t) * (1.f/Dd);
    float xn = d * rsqrtf(var + EPSf) * g[t] + b[t];
    g_x0[row*Dd + t] = xn;
    float sq = bred64(xn*xn, sred, t);
    if (t == 0) g_sq[row] = sq;
}

// ---------------- K1: pairwise distance keys (one 32x32 tile per block) ----------------
__global__ void __launch_bounds__(256) k_dist(int layer){
    const float* __restrict__ x = layer ? g_n1 : g_x0;
    __shared__ float sxi[32][68];
    __shared__ float sxjT[64][33];
    __shared__ float ssqj[32];
    int b  = blockIdx.z;
    int i0 = blockIdx.y * 32;
    int j0 = blockIdx.x * 32;
    int t  = threadIdx.x;
    {
        int il = t >> 3, c0 = (t & 7) * 8;
        const float* srci = x + (size_t)(b*Nn + i0 + il)*Dd + c0;
        float4 a0 = *(const float4*)srci;
        float4 a1 = *(const float4*)(srci + 4);
        *(float4*)&sxi[il][c0]   = a0;
        *(float4*)&sxi[il][c0+4] = a1;
        const float* srcj = x + (size_t)(b*Nn + j0 + il)*Dd + c0;
        float4 b0 = *(const float4*)srcj;
        float4 b1 = *(const float4*)(srcj + 4);
        sxjT[c0+0][il]=b0.x; sxjT[c0+1][il]=b0.y; sxjT[c0+2][il]=b0.z; sxjT[c0+3][il]=b0.w;
        sxjT[c0+4][il]=b1.x; sxjT[c0+5][il]=b1.y; sxjT[c0+6][il]=b1.z; sxjT[c0+7][il]=b1.w;
        if (t < 32) ssqj[t] = g_sq[b*Nn + j0 + t];
    }
    __syncthreads();
    int w = t >> 5, lane = t & 31;
    int ib = w * 4;
    float a0=0.f, a1=0.f, a2=0.f, a3=0.f;
    #pragma unroll
    for (int c4 = 0; c4 < 16; c4++){
        float4 x0 = *(const float4*)&sxi[ib+0][c4*4];
        float4 x1 = *(const float4*)&sxi[ib+1][c4*4];
        float4 x2 = *(const float4*)&sxi[ib+2][c4*4];
        float4 x3 = *(const float4*)&sxi[ib+3][c4*4];
        float r0 = sxjT[c4*4+0][lane];
        float r1 = sxjT[c4*4+1][lane];
        float r2 = sxjT[c4*4+2][lane];
        float r3 = sxjT[c4*4+3][lane];
        a0 += x0.x*r0 + x0.y*r1 + x0.z*r2 + x0.w*r3;
        a1 += x1.x*r0 + x1.y*r1 + x1.z*r2 + x1.w*r3;
        a2 += x2.x*r0 + x2.y*r1 + x2.z*r2 + x2.w*r3;
        a3 += x3.x*r0 + x3.y*r1 + x3.z*r2 + x3.w*r3;
    }
    float sj = ssqj[lane];
    size_t base = (size_t)(b*Nn + i0 + ib) * Nn + j0 + lane;
    g_d2[base + 0*Nn] = sj - 2.f*a0;
    g_d2[base + 1*Nn] = sj - 2.f*a1;
    g_d2[base + 2*Nn] = sj - 2.f*a2;
    g_d2[base + 3*Nn] = sj - 2.f*a3;
}

// ---------------- K2: top-16 smallest per row ----------------
__global__ void k_topk(){
    int w = threadIdx.x >> 5, lane = threadIdx.x & 31;
    int row = blockIdx.x * 4 + w;
    const float* r = g_d2 + (size_t)row * Nn + lane * 16;
    float v[16];
    #pragma unroll
    for (int u = 0; u < 4; u++){
        float4 a = *(const float4*)(r + u*4);
        v[u*4]=a.x; v[u*4+1]=a.y; v[u*4+2]=a.z; v[u*4+3]=a.w;
    }
    unsigned used = 0;
    const float INF = __int_as_float(0x7f800000);
    for (int sel = 0; sel < KK; sel++){
        float bv = INF; int bu = 16;
        #pragma unroll
        for (int u = 0; u < 16; u++){
            bool ok = !((used >> u) & 1u);
            if (ok && v[u] < bv){ bv = v[u]; bu = u; }
        }
        int gi = lane * 16 + bu;   // ties -> lowest j (stable, matches jax)
        #pragma unroll
        for (int o = 16; o; o >>= 1){
            float ov = __shfl_xor_sync(0xffffffffu, bv, o);
            int   og = __shfl_xor_sync(0xffffffffu, gi, o);
            if (ov < bv || (ov == bv && og < gi)){ bv = ov; gi = og; }
        }
        if ((gi >> 4) == lane) used |= 1u << (gi & 15);
        if (lane == 0) g_idx[row*KK + sel] = gi;
    }
}

// ---------------- K3: p = x@(Wt-Wb), q = x@Wb (smem-staged, float4 LDS) ----------------
__global__ void __launch_bounds__(256) k_pq(int layer, const float* __restrict__ mw){
    const float* __restrict__ x = layer ? g_n1 : g_x0;
    __shared__ __align__(16) float swd[4096];
    __shared__ __align__(16) float swb[4096];
    __shared__ __align__(16) float sx[1024];
    int t = threadIdx.x;
    for (int u = t; u < 1024; u += 256){
        float4 top = ((const float4*)mw)[u];
        float4 bot = ((const float4*)(mw + 4096))[u];
        float4 dd;
        dd.x = top.x - bot.x; dd.y = top.y - bot.y;
        dd.z = top.z - bot.z; dd.w = top.w - bot.w;
        ((float4*)swb)[u] = bot;
        ((float4*)swd)[u] = dd;
    }
    int rowbase = blockIdx.x * 16;
    ((float4*)sx)[t] = ((const float4*)(x + (size_t)rowbase*64))[t];
    __syncthreads();
    int r = t >> 4, d0 = (t & 15) * 4;
    float4 p = {0,0,0,0}, q = {0,0,0,0};
    #pragma unroll
    for (int c = 0; c < 64; c++){
        float xc = sx[r*64 + c];
        float4 wd = *(const float4*)&swd[c*64 + d0];
        float4 wb = *(const float4*)&swb[c*64 + d0];
        p.x += xc*wd.x; p.y += xc*wd.y; p.z += xc*wd.z; p.w += xc*wd.w;
        q.x += xc*wb.x; q.y += xc*wb.y; q.z += xc*wb.z; q.w += xc*wb.w;
    }
    *(float4*)&g_p[(size_t)(rowbase + r)*64 + d0] = p;
    *(float4*)&g_q[(size_t)(rowbase + r)*64 + d0] = q;
}

// ---------------- K4: BN partial stats ----------------
__global__ void __launch_bounds__(256) k_stats(){
    __shared__ int sidx[256];
    __shared__ float ssum[16][64], ssq2[16][64];
    int t = threadIdx.x;
    int rowbase = blockIdx.x * 16;
    sidx[t] = g_idx[rowbase*KK + t];
    __syncthreads();
    int rl = t >> 4, c0 = (t & 15) * 4;
    int row = rowbase + rl, b = row >> 9;
    float4 p = *(const float4*)&g_p[(size_t)row*64 + c0];
    float4 s = {0,0,0,0}, ss = {0,0,0,0};
    #pragma unroll
    for (int k = 0; k < KK; k++){
        int j = sidx[rl*KK + k];
        float4 qv = *(const float4*)&g_q[(size_t)(b*Nn + j)*64 + c0];
        float h0 = p.x + qv.x, h1 = p.y + qv.y, h2 = p.z + qv.z, h3 = p.w + qv.w;
        s.x += h0; s.y += h1; s.z += h2; s.w += h3;
        ss.x += h0*h0; ss.y += h1*h1; ss.z += h2*h2; ss.w += h3*h3;
    }
    *(float4*)&ssum[rl][c0] = s;
    *(float4*)&ssq2[rl][c0] = ss;
    __syncthreads();
    if (t < 64){
        float a = 0.f, bb = 0.f;
        #pragma unroll
        for (int r2 = 0; r2 < 16; r2++){ a += ssum[r2][t]; bb += ssq2[r2][t]; }
        g_part[blockIdx.x*128 + t]      = a;
        g_part[blockIdx.x*128 + 64 + t] = bb;
    }
}

// ---------------- K6: n_out = mean_k gelu(BN(p + q_nbr)); stats2 fused ----------------
__global__ void __launch_bounds__(256) k_nout(int layer, const float* __restrict__ gam,
                                              const float* __restrict__ bet,
                                              float* __restrict__ outH){
    __shared__ int sidx[256];
    __shared__ __align__(16) float sstats[128];
    __shared__ float stmp[2][128];
    int t = threadIdx.x;
    int rowbase = blockIdx.x * 16;
    {   // fused k_stats2: deterministic 2-phase reduction of g_part
        int c = t & 127, half = t >> 7;
        float s = 0.f;
        int b0 = half * 64;
        #pragma unroll 8
        for (int blk = b0; blk < b0 + 64; blk++) s += g_part[blk*128 + c];
        stmp[half][c] = s;
    }
    sidx[t] = g_idx[rowbase*KK + t];
    __syncthreads();
    if (t < 128) sstats[t] = stmp[0][t] + stmp[1][t];
    __syncthreads();
    int rl = t >> 4, c0 = (t & 15) * 4;
    int row = rowbase + rl, b = row >> 9;
    const float invN = 1.f / (float)(BN * KK);
    float4 st  = *(const float4*)&sstats[c0];
    float4 st2 = *(const float4*)&sstats[64 + c0];
    float4 ga  = *(const float4*)&gam[c0];
    float4 be  = *(const float4*)&bet[c0];
    float mu0 = st.x*invN, mu1 = st.y*invN, mu2 = st.z*invN, mu3 = st.w*invN;
    float rs0 = rsqrtf(st2.x*invN - mu0*mu0 + EPSf);
    float rs1 = rsqrtf(st2.y*invN - mu1*mu1 + EPSf);
    float rs2 = rsqrtf(st2.z*invN - mu2*mu2 + EPSf);
    float rs3 = rsqrtf(st2.w*invN - mu3*mu3 + EPSf);
    float4 p = *(const float4*)&g_p[(size_t)row*64 + c0];
    float4 acc = {0,0,0,0};
    #pragma unroll
    for (int k = 0; k < KK; k++){
        int j = sidx[rl*KK + k];
        float4 qv = *(const float4*)&g_q[(size_t)(b*Nn + j)*64 + c0];
        acc.x += gelu_exact((p.x + qv.x - mu0) * rs0 * ga.x + be.x);
        acc.y += gelu_exact((p.y + qv.y - mu1) * rs1 * ga.y + be.y);
        acc.z += gelu_exact((p.z + qv.z - mu2) * rs2 * ga.z + be.z);
        acc.w += gelu_exact((p.w + qv.w - mu3) * rs3 * ga.w + be.w);
    }
    float4 nv;
    nv.x = acc.x * (1.f/KK); nv.y = acc.y * (1.f/KK);
    nv.z = acc.z * (1.f/KK); nv.w = acc.w * (1.f/KK);
    if (layer){
        *(float4*)&g_n2[(size_t)row*64 + c0] = nv;
        *(float4*)&outH[(size_t)row*64 + c0] = nv;
    } else {
        *(float4*)&g_n1[(size_t)row*64 + c0] = nv;
        float sq = nv.x*nv.x + nv.y*nv.y + nv.z*nv.z + nv.w*nv.w;
        #pragma unroll
        for (int o = 8; o; o >>= 1) sq += __shfl_xor_sync(0xffffffffu, sq, o);
        if ((t & 15) == 0) g_sq[row] = sq;
    }
}

// ---------------- K8: A/Bt per row + (block 0) W, C fusion ----------------
__global__ void __launch_bounds__(256) k_abt(const float* __restrict__ hw,
                                             const float* __restrict__ hb){
    __shared__ float s_wn11[2048], s_wn21[2048], s_wn12[2048], s_wn22[2048], s_we2[1024];
    __shared__ float sn1[8][64], sn2[8][64], sa1[8][32], sb1[8][32];
    int t = threadIdx.x;
    for (int u = t; u < 2048; u += 256){
        s_wn11[u] = hw[1024 + u];
        s_wn21[u] = hw[3072 + u];
        s_wn12[u] = hw[5120 + 1024 + u];
        s_wn22[u] = hw[5120 + 3072 + u];
    }
    for (int u = t; u < 1024; u += 256) s_we2[u] = hw[5120 + u];
    int w = t >> 5, lane = t & 31;
    int row = blockIdx.x * 8 + w;
    sn1[w][lane]      = g_n1[(size_t)row*64 + lane];
    sn1[w][32 + lane] = g_n1[(size_t)row*64 + 32 + lane];
    sn2[w][lane]      = g_n2[(size_t)row*64 + lane];
    sn2[w][32 + lane] = g_n2[(size_t)row*64 + 32 + lane];
    __syncthreads();
    float a1 = 0.f, b1 = 0.f;
    #pragma unroll
    for (int d = 0; d < 64; d++){
        float nv = sn1[w][d];
        a1 += nv * s_wn11[d*32 + lane];
        b1 += nv * s_wn21[d*32 + lane];
    }
    sa1[w][lane] = a1; sb1[w][lane] = b1;
    __syncwarp();
    float A = 0.f, Bv = 0.f;
    #pragma unroll
    for (int e = 0; e < 32; e++){
        float w2 = s_we2[e*32 + lane];
        A  += sa1[w][e] * w2;
        Bv += sb1[w][e] * w2;
    }
    #pragma unroll
    for (int d = 0; d < 64; d++){
        float nv = sn2[w][d];
        A  += nv * s_wn12[d*32 + lane];
        Bv += nv * s_wn22[d*32 + lane];
    }
    g_A[(size_t)row*32 + lane]  = A;
    g_Bt[(size_t)row*32 + lane] = Bv;
    if (blockIdx.x == 0){
        for (int u = t; u < 1024; u += 256){
            int e = u >> 5, f = u & 31;
            float s = 0.f;
            #pragma unroll
            for (int m = 0; m < 32; m++) s += hw[e*32 + m] * s_we2[m*32 + f];
            g_W[u] = s;
        }
        if (t < 32){
            float c = hb[32 + t];
            #pragma unroll
            for (int m = 0; m < 32; m++) c += hb[m] * s_we2[m*32 + t];
            g_C[t] = c;
        }
    }
}

// ---------------- K10: big fused E pass — smem-staged tile, coalesced GMEM ----------------
// out_E[b,i,j,:] = LN(E[b,i,j,:]) @ W + A[b,j] + Bt[b,i] + C
// grid (32 jt, 32 it, 4 b), block 256 = tile 16i x 16j = 256 rows.
// E tile staged smem with pitch 36 floats (float4-aligned, conflict-free phases);
// thread t computes smem row t; output staged back through smem; coalesced STG.
__global__ void __launch_bounds__(256) k_bigE(const float* __restrict__ E,
                                              const float* __restrict__ lnEg,
                                              const float* __restrict__ lnEb,
                                              float* __restrict__ outE){
    __shared__ __align__(16) float stile[256*36];          // 36864 B
    __shared__ __align__(16) unsigned long long sW[512];   // [e][f2] packed pairs
    __shared__ __align__(8)  float sC[32];
    __shared__ float sg[32], sb[32];
    __shared__ __align__(16) float sA[16][36], sBt[16][36];
    int t = threadIdx.x;
    int b = blockIdx.z, i0 = blockIdx.y * 16, j0 = blockIdx.x * 16;
    {
        const unsigned long long* Wp = (const unsigned long long*)g_W;
        for (int u = t; u < 512; u += 256) sW[u] = Wp[u];
        if (t < 32){ sC[t] = g_C[t]; sg[t] = lnEg[t]; sb[t] = lnEb[t]; }
        for (int u = t; u < 512; u += 256){
            int r = u >> 5, f = u & 31;
            sA[r][f]  = g_A [(size_t)(b*Nn + j0 + r)*32 + f];
            sBt[r][f] = g_Bt[(size_t)(b*Nn + i0 + r)*32 + f];
        }
    }
    // coalesced stage-in: 16 chunks (one per i), each 16 rows x 32 floats contiguous
    {
        int f4 = t & 127;           // float4 index within chunk (0..127)
        int cp = t >> 7;            // chunk parity
        int jj = f4 >> 3, c4 = f4 & 7;
        #pragma unroll
        for (int it = 0; it < 8; it++){
            int ic = it*2 + cp;
            size_t grow = (size_t)(b*Nn + i0 + ic) * Nn + (j0 + jj);
            float4 val = ((const float4*)E)[grow*8 + c4];
            *(float4*)&stile[(ic*16 + jj)*36 + c4*4] = val;
        }
    }
    __syncthreads();
    int il = t >> 4, jl = t & 15;

    float v[32];
    float s = 0.f;
    #pragma unroll
    for (int u = 0; u < 8; u++){
        float4 a = *(const float4*)&stile[t*36 + u*4];
        v[u*4]=a.x; v[u*4+1]=a.y; v[u*4+2]=a.z; v[u*4+3]=a.w;
        s += a.x + a.y + a.z + a.w;
    }
    float mean = s * (1.f/32.f);
    float s2 = 0.f;
    #pragma unroll
    for (int u = 0; u < 32; u++){ float d = v[u] - mean; v[u] = d; s2 += d*d; }
    float rstd = rsqrtf(s2 * (1.f/32.f) + EPSf);
    #pragma unroll
    for (int u = 0; u < 32; u++) v[u] = v[u] * rstd * sg[u] + sb[u];

    // acc init = A + Bt + C  (packed f32x2)
    const unsigned long long* Ap  = (const unsigned long long*)&sA[jl][0];
    const unsigned long long* Bp  = (const unsigned long long*)&sBt[il][0];
    const unsigned long long* Cp  = (const unsigned long long*)sC;
    unsigned long long accp[16];
    #pragma unroll
    for (int f2 = 0; f2 < 16; f2++) accp[f2] = addf2(addf2(Ap[f2], Bp[f2]), Cp[f2]);

    #pragma unroll
    for (int e = 0; e < 32; e++){
        unsigned long long vv = dup2(v[e]);
        #pragma unroll
        for (int f2 = 0; f2 < 16; f2++) fmaf2(accp[f2], vv, sW[e*16 + f2]);
    }

    // results -> own smem row (only thread t touches row t between syncs)
    #pragma unroll
    for (int u = 0; u < 8; u++){
        unsigned long long lo = accp[u*2], hi = accp[u*2 + 1];
        float4 o;
        o.x = __uint_as_float((unsigned)lo);
        o.y = __uint_as_float((unsigned)(lo >> 32));
        o.z = __uint_as_float((unsigned)hi);
        o.w = __uint_as_float((unsigned)(hi >> 32));
        *(float4*)&stile[t*36 + u*4] = o;
    }
    __syncthreads();
    // coalesced stage-out
    {
        int f4 = t & 127;
        int cp = t >> 7;
        int jj = f4 >> 3, c4 = f4 & 7;
        #pragma unroll
        for (int it = 0; it < 8; it++){
            int ic = it*2 + cp;
            size_t grow = (size_t)(b*Nn + i0 + ic) * Nn + (j0 + jj);
            ((float4*)outE)[grow*8 + c4] = *(const float4*)&stile[(ic*16 + jj)*36 + c4*4];
        }
    }
}

// ---------------- launch ----------------
extern "C" void kernel_launch(void* const* d_in, const int* in_sizes, int n_in,
                              void* d_out, int out_size){
    const float* H    = (const float*)d_in[0];
    const float* E    = (const float*)d_in[1];
    const float* mlp  = (const float*)d_in[2];
    const float* bng  = (const float*)d_in[3];
    const float* bnb  = (const float*)d_in[4];
    const float* hw   = (const float*)d_in[5];
    const float* hb   = (const float*)d_in[6];
    const float* lnHg = (const float*)d_in[7];
    const float* lnHb = (const float*)d_in[8];
    const float* lnEg = (const float*)d_in[9];
    const float* lnEb = (const float*)d_in[10];
    float* outH = (float*)d_out;
    float* outE = outH + BN*Dd;

    k_lnH<<<BN, 64>>>(H, lnHg, lnHb);
    for (int l = 0; l < 2; l++){
        k_dist<<<dim3(16,16,4), 256>>>(l);
        k_topk<<<512, 128>>>();
        k_pq<<<128, 256>>>(l, mlp + l*2*Dd*Dd);
        k_stats<<<128, 256>>>();
        k_nout<<<128, 256>>>(l, bng + l*Dd, bnb + l*Dd, outH);
    }
    k_abt<<<256, 256>>>(hw, hb);
    k_bigE<<<dim3(32,32,4), 256>>>(E, lnEg, lnEb, outE);
}